// round 16
// baseline (speedup 1.0000x reference)
#include <cuda_runtime.h>
#include <cuda_bf16.h>
#include <cstdint>
#include <cstddef>

// ---------------------------------------------------------------------------
// BiLSTM-NER, Round 15 (R14 base, proven 2180us):
//  * A0 tile load split into two column-half commit groups; the fused mma
//    pass starts on half 1 while half 2 + A1 are still in flight (removes
//    the fully-exposed A0 wait from the interval critical path).
//  All other logic bit-identical to R14.
// ---------------------------------------------------------------------------

#define Tt 256
#define Bb 256
#define Hh 384
#define G4 1536   // 4*H
#define INP 100
#define Kc 10
#define NCTA_LSTM 96
#define NCTA_GEMM 52
#define NTILES (512 * 12)   // (M/128) * (G4/128)

typedef __nv_bfloat16 bf16;

// ============================ PTX helpers ==================================
__device__ __forceinline__ uint32_t smem_to_u32(const void* p) {
    uint32_t a;
    asm("{ .reg .u64 t; cvta.to.shared.u64 t, %1; cvt.u32.u64 %0, t; }"
        : "=r"(a) : "l"(p));
    return a;
}
__device__ __forceinline__ void ldsm4(uint32_t* r, uint32_t saddr) {
    asm volatile("ldmatrix.sync.aligned.m8n8.x4.shared.b16 {%0,%1,%2,%3}, [%4];"
        : "=r"(r[0]), "=r"(r[1]), "=r"(r[2]), "=r"(r[3]) : "r"(saddr));
}
__device__ __forceinline__ void mma_bf16(float* c, const uint32_t* a, const uint32_t* b) {
    asm volatile(
        "mma.sync.aligned.m16n8k16.row.col.f32.bf16.bf16.f32 "
        "{%0,%1,%2,%3}, {%4,%5,%6,%7}, {%8,%9}, {%0,%1,%2,%3};"
        : "+f"(c[0]), "+f"(c[1]), "+f"(c[2]), "+f"(c[3])
        : "r"(a[0]), "r"(a[1]), "r"(a[2]), "r"(a[3]), "r"(b[0]), "r"(b[1]));
}
#define CP_ASYNC16(sa, ga) \
    asm volatile("cp.async.cg.shared.global [%0], [%1], 16;" \
                 :: "r"(sa), "l"(ga) : "memory")
#define CP_COMMIT() asm volatile("cp.async.commit_group;" ::: "memory")
#define CP_WAIT0()  asm volatile("cp.async.wait_group 0;" ::: "memory")
#define CP_WAIT1()  asm volatile("cp.async.wait_group 1;" ::: "memory")
#define CP_WAIT2()  asm volatile("cp.async.wait_group 2;" ::: "memory")

__device__ __forceinline__ float tanh_ap(float x) {
    float y; asm("tanh.approx.f32 %0, %1;" : "=f"(y) : "f"(x)); return y;
}
__device__ __forceinline__ float sig_ap(float x) {
    return fmaf(tanh_ap(0.5f * x), 0.5f, 0.5f);
}
__device__ __forceinline__ void st_release_gpu(unsigned int* p, unsigned int v) {
    asm volatile("st.global.release.gpu.b32 [%0], %1;" :: "l"(p), "r"(v) : "memory");
}
__device__ __forceinline__ unsigned int ld_acquire_gpu(const unsigned int* p) {
    unsigned int v;
    asm volatile("ld.global.acquire.gpu.b32 %0, [%1];" : "=r"(v) : "l"(p) : "memory");
    return v;
}
__device__ __forceinline__ void red_release_gpu(unsigned int* p, unsigned int v) {
    asm volatile("red.release.gpu.global.add.u32 [%0], %1;" :: "l"(p), "r"(v) : "memory");
}
__device__ __forceinline__ void nsleep(unsigned int ns) {
    asm volatile("nanosleep.u32 %0;" :: "r"(ns));
}

// ------------------------- scratch (device globals) ------------------------
// xw permuted: xwP[((t*256+row)*192 + hc/2)*8 + gate*2 + q]  (bf16)
__device__ bf16  g_xwb[(size_t)Tt * Bb * G4];
__device__ bf16  g_h1b[(size_t)Tt * Bb * Hh];      // layer1 outputs (history)
__device__ float g_em[(size_t)Tt * Bb * Kc];       // emissions (fp32)
__device__ float g_wc1[Kc * 512];                  // W3 @ W2  (10 x 512)
__device__ float g_wc[Kc * Hh];                    // W3@W2@W1 (10 x 384)
__device__ float g_t1[1024];                       // W2 @ b1 + b2
__device__ float g_bc[Kc];                         // composed bias
__device__ bf16  g_h0buf[2 * Bb * Hh];             // recurrent h0 state (bf16)
__device__ float g_partial[Bb];

__device__ unsigned int g_flags[NCTA_LSTM * 32];   // one per CTA, own 128B line
__device__ unsigned int g_ready[Tt];               // xw tiles ready (24/step)

// ------------------------------ init state --------------------------------
__global__ void init_state_kernel() {
    int i = blockIdx.x * blockDim.x + threadIdx.x;
    if (i < 2 * Bb * Hh) g_h0buf[i] = __float2bfloat16(0.f);
    if (i < NCTA_LSTM * 32) g_flags[i] = 0u;
    if (i < Tt) g_ready[i] = 0u;
}

// -------------- MLP weight composition (warp per output) -------------------
__global__ __launch_bounds__(256) void compose1(
    const float* __restrict__ W3, const float* __restrict__ W2,
    const float* __restrict__ b1, const float* __restrict__ b2)
{
    int w = (blockIdx.x * blockDim.x + threadIdx.x) >> 5;
    int lane = threadIdx.x & 31;
    if (w < Kc * 512) {
        int r = w / 512, c = w - r * 512;
        float s = 0.f;
        for (int k = lane; k < 1024; k += 32)
            s += W3[r * 1024 + k] * W2[k * 512 + c];
#pragma unroll
        for (int off = 16; off; off >>= 1)
            s += __shfl_xor_sync(0xffffffffu, s, off);
        if (lane == 0) g_wc1[w] = s;
    } else if (w < Kc * 512 + 1024) {
        int j = w - Kc * 512;
        float s = 0.f;
        for (int k = lane; k < 512; k += 32)
            s += W2[j * 512 + k] * b1[k];
#pragma unroll
        for (int off = 16; off; off >>= 1)
            s += __shfl_xor_sync(0xffffffffu, s, off);
        if (lane == 0) g_t1[j] = s + b2[j];
    }
}
__global__ __launch_bounds__(256) void compose2(
    const float* __restrict__ W1, const float* __restrict__ W3,
    const float* __restrict__ b3)
{
    int w = (blockIdx.x * blockDim.x + threadIdx.x) >> 5;
    int lane = threadIdx.x & 31;
    if (w < Kc * Hh) {
        int r = w / Hh, c = w - r * Hh;
        float s = 0.f;
        for (int k = lane; k < 512; k += 32)
            s += g_wc1[r * 512 + k] * W1[k * Hh + c];
#pragma unroll
        for (int off = 16; off; off >>= 1)
            s += __shfl_xor_sync(0xffffffffu, s, off);
        if (lane == 0) g_wc[w] = s;
    } else if (w < Kc * Hh + Kc) {
        int r = w - Kc * Hh;
        float s = 0.f;
        for (int k = lane; k < 1024; k += 32)
            s += W3[r * 1024 + k] * g_t1[k];
#pragma unroll
        for (int off = 16; off; off >>= 1)
            s += __shfl_xor_sync(0xffffffffu, s, off);
        if (lane == 0) g_bc[r] = s + b3[r];
    }
}

// ------------- release/acquire group barrier (24 CTAs/group) ---------------
__device__ __forceinline__ void group_barrier(int grp, int cta_in_grid,
                                              unsigned int target) {
    __syncthreads();
    if (threadIdx.x < 32) {
        if (threadIdx.x == 0)
            st_release_gpu(&g_flags[cta_in_grid * 32], target);
        if (threadIdx.x < 24) {
            const unsigned int* f = &g_flags[(grp + threadIdx.x * 4) * 32];
            while (ld_acquire_gpu(f) < target) { }
        }
    }
    __syncthreads();
}

// ---------------- producer: inline-convert tile loader ---------------------
__device__ __forceinline__ void fill_chunk_conv(
    bf16* buf, const float* __restrict__ src, int base_row, int kt,
    int lrow, int lc)
{
#pragma unroll
    for (int it = 0; it < 2; it++) {
        int row = lrow + it * 64;
        int r = base_row + row;
        int k = kt * 32 + lc * 8;
        float v[8];
        if (k + 7 < INP) {
            float4 a = *(const float4*)(src + (size_t)r * INP + k);
            float4 b = *(const float4*)(src + (size_t)r * INP + k + 4);
            v[0] = a.x; v[1] = a.y; v[2] = a.z; v[3] = a.w;
            v[4] = b.x; v[5] = b.y; v[6] = b.z; v[7] = b.w;
        } else {
#pragma unroll
            for (int i = 0; i < 8; i++)
                v[i] = (k + i < INP) ? src[(size_t)r * INP + k + i] : 0.f;
        }
        __nv_bfloat162 h0 = __floats2bfloat162_rn(v[0], v[1]);
        __nv_bfloat162 h1 = __floats2bfloat162_rn(v[2], v[3]);
        __nv_bfloat162 h2 = __floats2bfloat162_rn(v[4], v[5]);
        __nv_bfloat162 h3 = __floats2bfloat162_rn(v[6], v[7]);
        uint4 pk;
        pk.x = *(uint32_t*)&h0; pk.y = *(uint32_t*)&h1;
        pk.z = *(uint32_t*)&h2; pk.w = *(uint32_t*)&h3;
        *(uint4*)(buf + row * 40 + lc * 8) = pk;
    }
}

// ---------------- producer role: xw0 GEMM + emissions + CRF ----------------
__device__ void producer_role(bf16* dsm, const float* __restrict__ x,
                              const float* __restrict__ Wih0,
                              const float* __restrict__ bih0,
                              const float* __restrict__ bhh0,
                              const int* __restrict__ tags,
                              const float* __restrict__ start_t,
                              const float* __restrict__ end_t,
                              const float* __restrict__ trans,
                              int worker)
{
    bf16* smA = dsm;                 // 128 x 40 (one 32-k chunk)
    bf16* smB = dsm + 5120;
    const uint32_t saddrA = smem_to_u32(smA);
    const uint32_t saddrB = smem_to_u32(smB);

    const int tid = threadIdx.x;
    const int lane = tid & 31;
    const int wid = tid >> 5;
    const int wm = wid & 3;
    const int wn = wid >> 2;

    const uint32_t a_off =
        (uint32_t)(((wm * 32 + (lane & 15)) * 40 + (lane >> 4) * 8) * 2);
    uint32_t b_off[4];
#pragma unroll
    for (int jp = 0; jp < 4; jp++)
        b_off[jp] = (uint32_t)(((wn * 64 + jp * 16 + (lane & 7) + ((lane >> 4) << 3)) * 40
                                + ((lane >> 3) & 1) * 8) * 2);
    const int lrow = tid >> 2;
    const int lc   = tid & 3;

    // ---- phase 1: xw0 GEMM tiles (inline fp32->bf16; PERMUTED output)
    for (int id = worker; id < NTILES; id += NCTA_GEMM) {
        const int t2 = id / 12;
        const int nb = id - t2 * 12;
        const int m0 = t2 * 128;
        const int n0 = nb * 128;
        const int gate = nb / 3;            // tile lies inside one gate block

        float acc[2][8][4];
#pragma unroll
        for (int i = 0; i < 2; i++)
#pragma unroll
            for (int j = 0; j < 8; j++)
#pragma unroll
                for (int q = 0; q < 4; q++) acc[i][j][q] = 0.f;

        for (int kt = 0; kt < 4; kt++) {
            fill_chunk_conv(smA, x,    m0, kt, lrow, lc);
            fill_chunk_conv(smB, Wih0, n0, kt, lrow, lc);
            __syncthreads();
#pragma unroll
            for (int kk = 0; kk < 2; kk++) {
                uint32_t a[2][4], b[4][4];
                ldsm4(a[0], saddrA + a_off + kk * 32);
                ldsm4(a[1], saddrA + a_off + 1280 + kk * 32);
#pragma unroll
                for (int jp = 0; jp < 4; jp++)
                    ldsm4(b[jp], saddrB + b_off[jp] + kk * 32);
#pragma unroll
                for (int mt = 0; mt < 2; mt++)
#pragma unroll
                    for (int j = 0; j < 8; j++)
                        mma_bf16(acc[mt][j], a[mt], &b[j >> 1][(j & 1) * 2]);
            }
            __syncthreads();
        }

#pragma unroll
        for (int mt = 0; mt < 2; mt++)
#pragma unroll
            for (int j = 0; j < 8; j++)
#pragma unroll
                for (int p = 0; p < 2; p++) {
                    int row = m0 + wm * 32 + mt * 16 + (lane >> 2) + p * 8;
                    int col = n0 + wn * 64 + j * 8 + (lane & 3) * 2;
                    int hc  = col - gate * Hh;
                    float v0 = acc[mt][j][p * 2]     + bih0[col]     + bhh0[col];
                    float v1 = acc[mt][j][p * 2 + 1] + bih0[col + 1] + bhh0[col + 1];
                    size_t dst = ((size_t)row * 192 + (hc >> 1)) * 8 + gate * 2;
                    *(__nv_bfloat162*)(g_xwb + dst) = __floats2bfloat162_rn(v0, v1);
                }

        __threadfence();
        __syncthreads();
        if (tid == 0) red_release_gpu(&g_ready[t2 >> 1], 1u);
    }

    // ---- phase 2+3: emissions + CRF per timestep, trailing the frontier
    for (int tau = worker; tau < Tt; tau += NCTA_GEMM) {
        if (tid < NCTA_LSTM) {
            while (ld_acquire_gpu(&g_flags[tid * 32]) < (unsigned int)(tau + 2))
                nsleep(256);
        }
        __syncthreads();

        for (int rr = wid; rr < Bb; rr += 8) {
            int row = tau * Bb + rr;
            float acc[Kc];
#pragma unroll
            for (int j = 0; j < Kc; j++) acc[j] = 0.f;
            const __nv_bfloat162* ar =
                (const __nv_bfloat162*)(g_h1b + (size_t)row * Hh);
#pragma unroll
            for (int it = 0; it < 6; it++) {
                int k2 = lane + it * 32;
                float2 a = __bfloat1622float2(ar[k2]);
#pragma unroll
                for (int j = 0; j < Kc; j++)
                    acc[j] += a.x * g_wc[j * Hh + 2 * k2]
                            + a.y * g_wc[j * Hh + 2 * k2 + 1];
            }
#pragma unroll
            for (int j = 0; j < Kc; j++) {
#pragma unroll
                for (int off = 16; off; off >>= 1)
                    acc[j] += __shfl_xor_sync(0xffffffffu, acc[j], off);
            }
            if (lane == 0) {
#pragma unroll
                for (int j = 0; j < Kc; j++)
                    g_em[(size_t)row * Kc + j] = acc[j] + g_bc[j];
            }
        }
        __syncthreads();

        if (wid == 0) {
            const float NEG = -1e30f;
            const float* em = g_em;
            float tr[Kc];
            int cl = (lane < Kc) ? lane : 0;
#pragma unroll
            for (int i = 0; i < Kc; i++) tr[i] = trans[i * Kc + cl];

            float a = (lane < Kc)
                ? (start_t[lane] + em[((size_t)tau * Tt) * Kc + lane]) : NEG;
            for (int tp = 1; tp < Tt; tp++) {
                float e = (lane < Kc) ? em[((size_t)tau * Tt + tp) * Kc + lane] : 0.f;
                float v[Kc];
                float m = NEG;
#pragma unroll
                for (int i = 0; i < Kc; i++) {
                    float ai = __shfl_sync(0xffffffffu, a, i);
                    v[i] = ai + tr[i];
                    m = fmaxf(m, v[i]);
                }
                float s = 0.f;
#pragma unroll
                for (int i = 0; i < Kc; i++) s += __expf(v[i] - m);
                float an = m + __logf(s) + e;
                a = (lane < Kc) ? an : NEG;
            }
            float z = (lane < Kc) ? (a + end_t[lane]) : NEG;
            float zmax = z;
#pragma unroll
            for (int off = 16; off; off >>= 1)
                zmax = fmaxf(zmax, __shfl_xor_sync(0xffffffffu, zmax, off));
            float zs = (lane < Kc) ? __expf(z - zmax) : 0.f;
#pragma unroll
            for (int off = 16; off; off >>= 1)
                zs += __shfl_xor_sync(0xffffffffu, zs, off);
            float logZ = zmax + __logf(zs);

            if (lane == 0) {
                int prev = tags[(size_t)tau * Tt];
                float score = start_t[prev] + em[((size_t)tau * Tt) * Kc + prev];
                for (int tp = 1; tp < Tt; tp++) {
                    int tg = tags[(size_t)tau * Tt + tp];
                    score += trans[prev * Kc + tg]
                           + em[((size_t)tau * Tt + tp) * Kc + tg];
                    prev = tg;
                }
                score += end_t[prev];
                g_partial[tau] = logZ - score;
            }
        }
        __syncthreads();
    }
}

// ================== fused 2-layer persistent LSTM + producer ===============
__global__ __launch_bounds__(256) void lstm_fused(
    const float* __restrict__ Whh0, const float* __restrict__ Wih1,
    const float* __restrict__ Whh1, const float* __restrict__ bih1,
    const float* __restrict__ bhh1, const float* __restrict__ bih0,
    const float* __restrict__ bhh0, const float* __restrict__ x,
    const float* __restrict__ Wih0, const int* __restrict__ tags,
    const float* __restrict__ start_t, const float* __restrict__ end_t,
    const float* __restrict__ trans)
{
    extern __shared__ bf16 dsm[];

    if (blockIdx.x >= NCTA_LSTM) {
        producer_role(dsm, x, Wih0, bih0, bhh0, tags, start_t, end_t, trans,
                      blockIdx.x - NCTA_LSTM);
        return;
    }

    bf16* W0sm  = dsm;                    // Whh0 slice  (64n x 392)
    bf16* Wi1sm = dsm + 64 * 392;         // Wih1 slice
    bf16* W1sm  = dsm + 2 * 64 * 392;     // Whh1 slice
    bf16* Asm   = dsm + 3 * 64 * 392;     // A0 tile (64 x 392)
    bf16* A1sm  = dsm + 4 * 64 * 392;     // h1 k-tiles 0..11 (64 x 200)
    const uint32_t w0base  = smem_to_u32(W0sm);
    const uint32_t wi1base = smem_to_u32(Wi1sm);
    const uint32_t w1base  = smem_to_u32(W1sm);
    const uint32_t abase   = smem_to_u32(Asm);
    const uint32_t a1base  = smem_to_u32(A1sm);

    const int tid = threadIdx.x;
    const int lane = tid & 31;
    const int wid = tid >> 5;
    const int wm = wid & 3;              // 16-row m tile
    const int wn = wid >> 2;             // h-col half (0/1)
    const int bx = blockIdx.x & 3;
    const int by = blockIdx.x >> 2;
    const int b0 = bx * 64;
    const int c0 = by * 16;

    for (int idx = tid; idx < 64 * 384; idx += 256) {
        int n = idx / 384, k = idx - n * 384;
        int g = n >> 4, hc = n & 15;
        size_t grow = (size_t)(g * Hh + c0 + hc) * Hh + k;
        int d = n * 392 + k;
        W0sm[d]  = __float2bfloat16(Whh0[grow]);
        Wi1sm[d] = __float2bfloat16(Wih1[grow]);
        W1sm[d]  = __float2bfloat16(Whh1[grow]);
    }

    const uint32_t a_off =
        (uint32_t)(((wm * 16 + (lane & 15)) * 392 + (lane >> 4) * 8) * 2);
    const uint32_t a1_off =
        (uint32_t)(((wm * 16 + (lane & 15)) * 200 + (lane >> 4) * 8) * 2);
    const uint32_t b_k = ((lane >> 3) & 1) * 8;
    const uint32_t b_off0 =
        (uint32_t)((((0 + (lane >> 4)) * 16 + wn * 8 + (lane & 7)) * 392 + b_k) * 2);
    const uint32_t b_off1 =
        (uint32_t)((((2 + (lane >> 4)) * 16 + wn * 8 + (lane & 7)) * 392 + b_k) * 2);

    const int prow = lane >> 2;
    const int pcol = (lane & 3) * 2;
    const int colg = c0 + wn * 8 + pcol;

    float bi1[4][2];
#pragma unroll
    for (int g = 0; g < 4; g++)
#pragma unroll
        for (int q = 0; q < 2; q++)
            bi1[g][q] = bih1[g * Hh + colg + q] + bhh1[g * Hh + colg + q];

    float cst0[4], cst1[4];
#pragma unroll
    for (int i = 0; i < 4; i++) { cst0[i] = 0.f; cst1[i] = 0.f; }

    for (int t = 0; t <= Tt; t++) {
        const int ph = t & 1;
        const bool doL0 = (t < Tt);
        const bool doL1 = (t >= 1);
        const bool doW  = (t >= 2);     // Whh1 pass (h1(t-2) exists)

        // ---- issue A0 half1 (cols 0..191) -> group Ga
        {
            const bf16* hprev0 = g_h0buf + (size_t)ph * Bb * Hh;
#pragma unroll
            for (int it = 0; it < 6; it++) {
                int idx = tid + it * 256;
                int row = idx / 24, c = idx - row * 24;
                CP_ASYNC16(abase + (uint32_t)((row * 392 + c * 8) * 2),
                           hprev0 + (size_t)(b0 + row) * Hh + c * 8);
            }
            CP_COMMIT();
            // ---- A0 half2 (cols 192..383) -> group Gb
#pragma unroll
            for (int it = 0; it < 6; it++) {
                int idx = tid + it * 256;
                int row = idx / 24, c = idx - row * 24;
                CP_ASYNC16(abase + (uint32_t)((row * 392 + 192 + c * 8) * 2),
                           hprev0 + (size_t)(b0 + row) * Hh + 192 + c * 8);
            }
            CP_COMMIT();
        }
        if (doW) {
            // ---- A1 <- h1(t-2) k-tiles 0..11 -> group Gc
            const bf16* hprev1 = g_h1b + (size_t)(t - 2) * Bb * Hh;
#pragma unroll
            for (int it = 0; it < 6; it++) {
                int idx = tid + it * 256;
                int row = idx / 24, c = idx - row * 24;
                CP_ASYNC16(a1base + (uint32_t)(row * 400 + c * 16),
                           hprev1 + (size_t)(b0 + row) * Hh + c * 8);
            }
            CP_COMMIT();
        }

        // ---- gate on producer-published xw(t)
        if (doL0) {
            if (tid == 0) {
                while (ld_acquire_gpu(&g_ready[t]) < 24u) { }
            }
        }
        __syncthreads();

        // ---- xw(t) fragments: ONE uint4 per row (permuted layout)
        float2 xv[4][2];
        if (doL0) {
#pragma unroll
            for (int p = 0; p < 2; p++) {
                int brow = b0 + wm * 16 + prow + p * 8;
                uint4 pk = *(const uint4*)(g_xwb +
                    (((size_t)t * Bb + brow) * 192 + (colg >> 1)) * 8);
                xv[0][p] = __bfloat1622float2(*(__nv_bfloat162*)&pk.x);
                xv[1][p] = __bfloat1622float2(*(__nv_bfloat162*)&pk.y);
                xv[2][p] = __bfloat1622float2(*(__nv_bfloat162*)&pk.z);
                xv[3][p] = __bfloat1622float2(*(__nv_bfloat162*)&pk.w);
            }
        }

        float accL0[4][4], accL1[4][4];
#pragma unroll
        for (int j = 0; j < 4; j++)
#pragma unroll
            for (int q = 0; q < 4; q++) { accL0[j][q] = 0.f; accL1[j][q] = 0.f; }

        // ---- wait A0 half1 only (Gb [, Gc] still in flight)
        if (doW) CP_WAIT2(); else CP_WAIT1();
        __syncthreads();

        // ---- fused pass kt 0..11 (A0 cols 0..191)
#pragma unroll 4
        for (int kt = 0; kt < 12; kt++) {
            uint32_t koff = (uint32_t)(kt * 32);
            uint32_t a[4], p0[4], p1[4], q0[4], q1[4];
            ldsm4(a, abase + a_off + koff);
            ldsm4(p0, w0base + b_off0 + koff);
            ldsm4(p1, w0base + b_off1 + koff);
            ldsm4(q0, wi1base + b_off0 + koff);
            ldsm4(q1, wi1base + b_off1 + koff);
            mma_bf16(accL0[0], a, &p0[0]);
            mma_bf16(accL1[0], a, &q0[0]);
            mma_bf16(accL0[1], a, &p0[2]);
            mma_bf16(accL1[1], a, &q0[2]);
            mma_bf16(accL0[2], a, &p1[0]);
            mma_bf16(accL1[2], a, &q1[0]);
            mma_bf16(accL0[3], a, &p1[2]);
            mma_bf16(accL1[3], a, &q1[2]);
        }

        // ---- wait A0 half2 ([Gc] still in flight)
        if (doW) CP_WAIT1(); else CP_WAIT0();
        __syncthreads();

        // ---- fused pass kt 12..23 (A0 cols 192..383)
#pragma unroll 4
        for (int kt = 12; kt < 24; kt++) {
            uint32_t koff = (uint32_t)(kt * 32);
            uint32_t a[4], p0[4], p1[4], q0[4], q1[4];
            ldsm4(a, abase + a_off + koff);
            ldsm4(p0, w0base + b_off0 + koff);
            ldsm4(p1, w0base + b_off1 + koff);
            ldsm4(q0, wi1base + b_off0 + koff);
            ldsm4(q1, wi1base + b_off1 + koff);
            mma_bf16(accL0[0], a, &p0[0]);
            mma_bf16(accL1[0], a, &q0[0]);
            mma_bf16(accL0[1], a, &p0[2]);
            mma_bf16(accL1[1], a, &q0[2]);
            mma_bf16(accL0[2], a, &p1[0]);
            mma_bf16(accL1[2], a, &q1[0]);
            mma_bf16(accL0[3], a, &p1[2]);
            mma_bf16(accL1[3], a, &q1[2]);
        }
        __syncthreads();    // all warps done reading A0 upper cols

        // ---- issue h1-upper (k-tiles 12..23) into A0 cols 192..383 -> Gd
        if (doW) {
            const bf16* hprev1 = g_h1b + (size_t)(t - 2) * Bb * Hh;
#pragma unroll
            for (int it = 0; it < 6; it++) {
                int idx = tid + it * 256;
                int row = idx / 24, c = idx - row * 24;
                CP_ASYNC16(abase + (uint32_t)(row * 784 + 384 + c * 16),
                           hprev1 + (size_t)(b0 + row) * Hh + 192 + c * 8);
            }
            CP_COMMIT();
        }

        // ---- Whh1 first chunk on A1 (wait Gc; Gd in flight)
        if (doW) {
            CP_WAIT1();
            __syncthreads();
#pragma unroll 4
            for (int kt = 0; kt < 12; kt++) {
                uint32_t koff = (uint32_t)(kt * 32);
                uint32_t a[4], b0v[4], b1v[4];
                ldsm4(a, a1base + a1_off + koff);
                ldsm4(b0v, w1base + b_off0 + koff);
                ldsm4(b1v, w1base + b_off1 + koff);
                mma_bf16(accL1[0], a, &b0v[0]);
                mma_bf16(accL1[1], a, &b0v[2]);
                mma_bf16(accL1[2], a, &b1v[0]);
                mma_bf16(accL1[3], a, &b1v[2]);
            }
        }

        // ---- L0 pointwise: h0(t) -> h0buf[ph^1]
        if (doL0) {
            bf16* hnext0 = g_h0buf + (size_t)(ph ^ 1) * Bb * Hh;
#pragma unroll
            for (int p = 0; p < 2; p++) {
                int brow = b0 + wm * 16 + prow + p * 8;
                float hnv[2];
#pragma unroll
                for (int q = 0; q < 2; q++) {
                    float xi = q ? xv[0][p].y : xv[0][p].x;
                    float xf = q ? xv[1][p].y : xv[1][p].x;
                    float xg = q ? xv[2][p].y : xv[2][p].x;
                    float xo = q ? xv[3][p].y : xv[3][p].x;
                    float i_ = sig_ap(accL0[0][p * 2 + q] + xi);
                    float f_ = sig_ap(accL0[1][p * 2 + q] + xf);
                    float g_ = tanh_ap(accL0[2][p * 2 + q] + xg);
                    float o_ = sig_ap(accL0[3][p * 2 + q] + xo);
                    float cn = f_ * cst0[p * 2 + q] + i_ * g_;
                    cst0[p * 2 + q] = cn;
                    hnv[q] = o_ * tanh_ap(cn);
                }
                *(__nv_bfloat162*)(hnext0 + (size_t)brow * Hh + colg) =
                    __floats2bfloat162_rn(hnv[0], hnv[1]);
            }
        }

        if (doL1) {
            if (doW) {
                CP_WAIT0();
                __syncthreads();
#pragma unroll 4
                for (int kt = 12; kt < 24; kt++) {
                    uint32_t koff = (uint32_t)(kt * 32);
                    uint32_t a[4], b0v[4], b1v[4];
                    ldsm4(a, abase + a_off + koff);
                    ldsm4(b0v, w1base + b_off0 + koff);
                    ldsm4(b1v, w1base + b_off1 + koff);
                    mma_bf16(accL1[0], a, &b0v[0]);
                    mma_bf16(accL1[1], a, &b0v[2]);
                    mma_bf16(accL1[2], a, &b1v[0]);
                    mma_bf16(accL1[3], a, &b1v[2]);
                }
            }

            bf16* houtp = g_h1b + (size_t)(t - 1) * Bb * Hh;
#pragma unroll
            for (int p = 0; p < 2; p++) {
                int brow = b0 + wm * 16 + prow + p * 8;
                float hnv[2];
#pragma unroll
                for (int q = 0; q < 2; q++) {
                    float i_ = sig_ap(accL1[0][p * 2 + q] + bi1[0][q]);
                    float f_ = sig_ap(accL1[1][p * 2 + q] + bi1[1][q]);
                    float g_ = tanh_ap(accL1[2][p * 2 + q] + bi1[2][q]);
                    float o_ = sig_ap(accL1[3][p * 2 + q] + bi1[3][q]);
                    float cn = f_ * cst1[p * 2 + q] + i_ * g_;
                    cst1[p * 2 + q] = cn;
                    hnv[q] = o_ * tanh_ap(cn);
                }
                *(__nv_bfloat162*)(houtp + (size_t)brow * Hh + colg) =
                    __floats2bfloat162_rn(hnv[0], hnv[1]);
            }
        }

        group_barrier(bx, blockIdx.x, (unsigned int)(t + 1));
    }
}

// ------------------------------ reduce -------------------------------------
__global__ __launch_bounds__(256) void reduce_kernel(float* __restrict__ out)
{
    __shared__ float sh[256];
    int i = threadIdx.x;
    sh[i] = g_partial[i];
    __syncthreads();
#pragma unroll
    for (int s = 128; s; s >>= 1) {
        if (i < s) sh[i] += sh[i + s];
        __syncthreads();
    }
    if (i == 0) out[0] = sh[0];
}

// ------------------------------ launch -------------------------------------
extern "C" void kernel_launch(void* const* d_in, const int* in_sizes, int n_in,
                              void* d_out, int out_size)
{
    (void)in_sizes; (void)n_in; (void)out_size;
    const float* x    = (const float*)d_in[0];
    const int*   tags = (const int*)d_in[2];
    const float* Wih0 = (const float*)d_in[3];
    const float* Whh0 = (const float*)d_in[4];
    const float* bih0 = (const float*)d_in[5];
    const float* bhh0 = (const float*)d_in[6];
    const float* Wih1 = (const float*)d_in[7];
    const float* Whh1 = (const float*)d_in[8];
    const float* bih1 = (const float*)d_in[9];
    const float* bhh1 = (const float*)d_in[10];
    const float* W1   = (const float*)d_in[11];
    const float* b1   = (const float*)d_in[12];
    const float* W2   = (const float*)d_in[13];
    const float* b2   = (const float*)d_in[14];
    const float* W3   = (const float*)d_in[15];
    const float* b3   = (const float*)d_in[16];
    const float* st   = (const float*)d_in[17];
    const float* et   = (const float*)d_in[18];
    const float* trn  = (const float*)d_in[19];

    const size_t LSTM_SMEM = (size_t)(4 * 64 * 392 + 64 * 200) * sizeof(bf16);
    cudaFuncSetAttribute(lstm_fused, cudaFuncAttributeMaxDynamicSharedMemorySize,
                         (int)LSTM_SMEM);

    init_state_kernel<<<(2 * Bb * Hh + 255) / 256, 256>>>();                  // 0
    compose1<<<((Kc * 512 + 1024) * 32 + 255) / 256, 256>>>(W3, W2, b1, b2);  // 1
    compose2<<<((Kc * Hh + Kc) * 32 + 255) / 256, 256>>>(W1, W3, b3);         // 2

    // fused: 96 LSTM CTAs + 52 producer CTAs (xw0 GEMM -> emissions -> CRF)
    lstm_fused<<<NCTA_LSTM + NCTA_GEMM, 256, LSTM_SMEM>>>(                    // 3
        Whh0, Wih1, Whh1, bih1, bhh1, bih0, bhh0, x, Wih0, tags, st, et, trn);

    reduce_kernel<<<1, 256>>>((float*)d_out);                                 // 4
}